// round 3
// baseline (speedup 1.0000x reference)
#include <cuda_runtime.h>
#include <cuda_bf16.h>
#include <cstdint>
#include <math.h>

#define Dd    2048
#define NTOK  4096
#define Sq    1024
#define HDh   64
#define NBH   128
#define EPSV  1e-5f
#define INV_SQRT_D 0.022097086912079608f

// ---------------- scratch ---------------------------------------------------
__device__ float g_x2[(size_t)NTOK * Dd];
__device__ __nv_bfloat16 g_hh [(size_t)NTOK * Dd], g_hl [(size_t)NTOK * Dd];
__device__ __nv_bfloat16 g_h2h[(size_t)NTOK * Dd], g_h2l[(size_t)NTOK * Dd];
__device__ __nv_bfloat16 g_f1h[(size_t)NTOK * Dd], g_f1l[(size_t)NTOK * Dd];
__device__ __nv_bfloat16 g_qh [(size_t)NTOK * Dd], g_ql [(size_t)NTOK * Dd];
__device__ __nv_bfloat16 g_kh [(size_t)NTOK * Dd], g_kl [(size_t)NTOK * Dd];
__device__ __nv_bfloat16 g_wqh[(size_t)Dd * Dd], g_wql[(size_t)Dd * Dd];
__device__ __nv_bfloat16 g_wkh[(size_t)Dd * Dd], g_wkl[(size_t)Dd * Dd];
__device__ __nv_bfloat16 g_w1h[(size_t)Dd * Dd], g_w1l[(size_t)Dd * Dd];
__device__ __nv_bfloat16 g_w2h[(size_t)Dd * Dd], g_w2l[(size_t)Dd * Dd];

// ---------------- helpers ----------------------------------------------------
__device__ __forceinline__ uint32_t smem_u32(const void* p) {
    return (uint32_t)__cvta_generic_to_shared(p);
}
__device__ __forceinline__ void cp16(uint32_t dst, const void* src) {
    asm volatile("cp.async.cg.shared.global [%0], [%1], 16;" :: "r"(dst), "l"(src));
}
__device__ __forceinline__ void cp_commit() {
    asm volatile("cp.async.commit_group;");
}
template<int N> __device__ __forceinline__ void cp_wait() {
    asm volatile("cp.async.wait_group %0;" :: "n"(N));
}
__device__ __forceinline__ void ldmx4(uint32_t a, uint32_t& r0, uint32_t& r1,
                                      uint32_t& r2, uint32_t& r3) {
    asm volatile("ldmatrix.sync.aligned.m8n8.x4.shared.b16 {%0,%1,%2,%3},[%4];"
                 : "=r"(r0), "=r"(r1), "=r"(r2), "=r"(r3) : "r"(a));
}
__device__ __forceinline__ void ldmx4t(uint32_t a, uint32_t& r0, uint32_t& r1,
                                       uint32_t& r2, uint32_t& r3) {
    asm volatile("ldmatrix.sync.aligned.m8n8.x4.trans.shared.b16 {%0,%1,%2,%3},[%4];"
                 : "=r"(r0), "=r"(r1), "=r"(r2), "=r"(r3) : "r"(a));
}
__device__ __forceinline__ void mma16816(float* c, const uint32_t* a, const uint32_t* b) {
    asm volatile(
        "mma.sync.aligned.m16n8k16.row.col.f32.bf16.bf16.f32 "
        "{%0,%1,%2,%3},{%4,%5,%6,%7},{%8,%9},{%0,%1,%2,%3};"
        : "+f"(c[0]), "+f"(c[1]), "+f"(c[2]), "+f"(c[3])
        : "r"(a[0]), "r"(a[1]), "r"(a[2]), "r"(a[3]), "r"(b[0]), "r"(b[1]));
}
__device__ __forceinline__ void split2(float v0, float v1,
                                       __nv_bfloat162& hi, __nv_bfloat162& lo) {
    __nv_bfloat16 h0 = __float2bfloat16(v0);
    __nv_bfloat16 h1 = __float2bfloat16(v1);
    __nv_bfloat16 l0 = __float2bfloat16(v0 - __bfloat162float(h0));
    __nv_bfloat16 l1 = __float2bfloat16(v1 - __bfloat162float(h1));
    hi.x = h0; hi.y = h1; lo.x = l0; lo.y = l1;
}
__device__ __forceinline__ void split_store4(__nv_bfloat16* hi, __nv_bfloat16* lo,
                                             size_t idx, float4 v) {
    __nv_bfloat162 h01, l01, h23, l23;
    split2(v.x, v.y, h01, l01);
    split2(v.z, v.w, h23, l23);
    *(__nv_bfloat162*)(hi + idx)     = h01;
    *(__nv_bfloat162*)(hi + idx + 2) = h23;
    *(__nv_bfloat162*)(lo + idx)     = l01;
    *(__nv_bfloat162*)(lo + idx + 2) = l23;
}

// ---------------- weight split ----------------------------------------------
__global__ __launch_bounds__(256) void splitf(const float4* __restrict__ W,
                                              __nv_bfloat16* __restrict__ hi,
                                              __nv_bfloat16* __restrict__ lo, int n4) {
    int i = blockIdx.x * 256 + threadIdx.x;
    if (i >= n4) return;
    split_store4(hi, lo, (size_t)i * 4, W[i]);
}

// ---------------- fused LN1 / residual / LN2 ---------------------------------
__global__ __launch_bounds__(256) void ln_fused(
    const float* __restrict__ x,
    const float* __restrict__ s1, const float* __restrict__ b1,
    const float* __restrict__ s2, const float* __restrict__ b2)
{
    __shared__ float rbuf[16];
    __shared__ float stats[2];
    const int tid = threadIdx.x;
    const size_t base = (size_t)blockIdx.x * Dd;
    const float4* xr = (const float4*)(x + base);
    float4 a0 = xr[tid];
    float4 a1 = xr[tid + 256];

    float s = a0.x + a0.y + a0.z + a0.w + a1.x + a1.y + a1.z + a1.w;
    float q = a0.x*a0.x + a0.y*a0.y + a0.z*a0.z + a0.w*a0.w
            + a1.x*a1.x + a1.y*a1.y + a1.z*a1.z + a1.w*a1.w;
    #pragma unroll
    for (int o = 16; o; o >>= 1) {
        s += __shfl_xor_sync(0xffffffffu, s, o);
        q += __shfl_xor_sync(0xffffffffu, q, o);
    }
    if ((tid & 31) == 0) { rbuf[tid >> 5] = s; rbuf[8 + (tid >> 5)] = q; }
    __syncthreads();
    if (tid == 0) {
        float ss = 0.f, qq = 0.f;
        #pragma unroll
        for (int i = 0; i < 8; i++) { ss += rbuf[i]; qq += rbuf[8 + i]; }
        float m = ss * (1.0f / Dd);
        stats[0] = m;
        stats[1] = rsqrtf(qq * (1.0f / Dd) - m * m + EPSV);
    }
    __syncthreads();
    float m = stats[0], r = stats[1];

    const float4* s1v = (const float4*)s1;
    const float4* b1v = (const float4*)b1;
    float4 sc0 = s1v[tid], sc1 = s1v[tid + 256];
    float4 bi0 = b1v[tid], bi1 = b1v[tid + 256];

    float4 h0, h1, x20, x21;
    h0.x = (a0.x - m) * r * sc0.x + bi0.x;  h0.y = (a0.y - m) * r * sc0.y + bi0.y;
    h0.z = (a0.z - m) * r * sc0.z + bi0.z;  h0.w = (a0.w - m) * r * sc0.w + bi0.w;
    h1.x = (a1.x - m) * r * sc1.x + bi1.x;  h1.y = (a1.y - m) * r * sc1.y + bi1.y;
    h1.z = (a1.z - m) * r * sc1.z + bi1.z;  h1.w = (a1.w - m) * r * sc1.w + bi1.w;
    x20.x = h0.x + a0.x; x20.y = h0.y + a0.y; x20.z = h0.z + a0.z; x20.w = h0.w + a0.w;
    x21.x = h1.x + a1.x; x21.y = h1.y + a1.y; x21.z = h1.z + a1.z; x21.w = h1.w + a1.w;

    split_store4(g_hh, g_hl, base + (size_t)tid * 4, h0);
    split_store4(g_hh, g_hl, base + (size_t)(tid + 256) * 4, h1);
    ((float4*)(g_x2 + base))[tid]       = x20;
    ((float4*)(g_x2 + base))[tid + 256] = x21;

    s = x20.x + x20.y + x20.z + x20.w + x21.x + x21.y + x21.z + x21.w;
    q = x20.x*x20.x + x20.y*x20.y + x20.z*x20.z + x20.w*x20.w
      + x21.x*x21.x + x21.y*x21.y + x21.z*x21.z + x21.w*x21.w;
    #pragma unroll
    for (int o = 16; o; o >>= 1) {
        s += __shfl_xor_sync(0xffffffffu, s, o);
        q += __shfl_xor_sync(0xffffffffu, q, o);
    }
    if ((tid & 31) == 0) { rbuf[tid >> 5] = s; rbuf[8 + (tid >> 5)] = q; }
    __syncthreads();
    if (tid == 0) {
        float ss = 0.f, qq = 0.f;
        #pragma unroll
        for (int i = 0; i < 8; i++) { ss += rbuf[i]; qq += rbuf[8 + i]; }
        float mm = ss * (1.0f / Dd);
        stats[0] = mm;
        stats[1] = rsqrtf(qq * (1.0f / Dd) - mm * mm + EPSV);
    }
    __syncthreads();
    m = stats[0]; r = stats[1];

    const float4* s2v = (const float4*)s2;
    const float4* b2v = (const float4*)b2;
    sc0 = s2v[tid]; sc1 = s2v[tid + 256];
    bi0 = b2v[tid]; bi1 = b2v[tid + 256];
    float4 o0, o1;
    o0.x = (x20.x - m) * r * sc0.x + bi0.x;  o0.y = (x20.y - m) * r * sc0.y + bi0.y;
    o0.z = (x20.z - m) * r * sc0.z + bi0.z;  o0.w = (x20.w - m) * r * sc0.w + bi0.w;
    o1.x = (x21.x - m) * r * sc1.x + bi1.x;  o1.y = (x21.y - m) * r * sc1.y + bi1.y;
    o1.z = (x21.z - m) * r * sc1.z + bi1.z;  o1.w = (x21.w - m) * r * sc1.w + bi1.w;
    split_store4(g_h2h, g_h2l, base + (size_t)tid * 4, o0);
    split_store4(g_h2h, g_h2l, base + (size_t)(tid + 256) * 4, o1);
}

// -----------------------------------------------------------------------------
// bf16 split-3 GEMM with cp.async double-buffered smem.
// Block tile 128x128, BK=32, 256 threads = 8 warps (2Mx4N), warp tile 64x32.
// Dynamic smem layout (elements):
//   Ah[buf]: buf*5120;  Al[buf]: 10240+buf*5120
//   Bh[buf]: 20480+buf*4352;  Bl[buf]: 29184+buf*4352   total 37888 el = 75776 B
// -----------------------------------------------------------------------------
#define A_EL 5120
#define B_EL 4352
#define GEMM_SMEM 75776

template<int EPI>
__global__ __launch_bounds__(256) void gemm3(
    int M, int N, int K,
    const __nv_bfloat16* __restrict__ Ah, const __nv_bfloat16* __restrict__ Al,
    const __nv_bfloat16* __restrict__ Bh, const __nv_bfloat16* __restrict__ Bl,
    float* __restrict__ C,
    const float* __restrict__ bias, const float* __restrict__ addm,
    __nv_bfloat16* __restrict__ Ohi, __nv_bfloat16* __restrict__ Olo)
{
    extern __shared__ __align__(16) char dsm[];
    const uint32_t sb = smem_u32(dsm);

    const int tid = threadIdx.x;
    const int m0 = blockIdx.y * 128, n0 = blockIdx.x * 128;
    const int s0 = tid, s1 = tid + 256;

    const __nv_bfloat16* gAh0 = Ah + (size_t)(m0 + (s0 >> 2)) * K + (s0 & 3) * 8;
    const __nv_bfloat16* gAh1 = Ah + (size_t)(m0 + (s1 >> 2)) * K + (s1 & 3) * 8;
    const __nv_bfloat16* gAl0 = Al + (size_t)(m0 + (s0 >> 2)) * K + (s0 & 3) * 8;
    const __nv_bfloat16* gAl1 = Al + (size_t)(m0 + (s1 >> 2)) * K + (s1 & 3) * 8;
    const __nv_bfloat16* gBh0 = Bh + (size_t)(s0 >> 4) * N + n0 + (s0 & 15) * 8;
    const __nv_bfloat16* gBh1 = Bh + (size_t)(s1 >> 4) * N + n0 + (s1 & 15) * 8;
    const __nv_bfloat16* gBl0 = Bl + (size_t)(s0 >> 4) * N + n0 + (s0 & 15) * 8;
    const __nv_bfloat16* gBl1 = Bl + (size_t)(s1 >> 4) * N + n0 + (s1 & 15) * 8;

    const uint32_t sa0 = ((s0 >> 2) * 40 + (s0 & 3) * 8) * 2;
    const uint32_t sa1 = ((s1 >> 2) * 40 + (s1 & 3) * 8) * 2;
    const uint32_t sb0 = ((s0 >> 4) * 136 + (s0 & 15) * 8) * 2;
    const uint32_t sb1 = ((s1 >> 4) * 136 + (s1 & 15) * 8) * 2;

    const int lane = tid & 31;
    const int wid = tid >> 5;
    const int wm = (wid & 1) * 64;
    const int wn = (wid >> 1) * 32;

    const uint32_t aOff = ((wm + (lane & 15)) * 40 + ((lane >> 4) << 3)) * 2;
    const uint32_t bOff = (((lane & 15)) * 136 + wn + ((lane >> 4) << 3)) * 2;

    float acc[4][4][4];
    #pragma unroll
    for (int i = 0; i < 4; i++)
        #pragma unroll
        for (int j = 0; j < 4; j++)
            #pragma unroll
            for (int t = 0; t < 4; t++) acc[i][j][t] = 0.f;

    auto ISSUE = [&](int k0, int buf) {
        uint32_t ah = sb + (buf * A_EL) * 2;
        uint32_t al = sb + (10240 + buf * A_EL) * 2;
        uint32_t bh = sb + (20480 + buf * B_EL) * 2;
        uint32_t bl = sb + (29184 + buf * B_EL) * 2;
        cp16(ah + sa0, gAh0 + k0);  cp16(ah + sa1, gAh1 + k0);
        cp16(al + sa0, gAl0 + k0);  cp16(al + sa1, gAl1 + k0);
        cp16(bh + sb0, gBh0 + (size_t)k0 * N);  cp16(bh + sb1, gBh1 + (size_t)k0 * N);
        cp16(bl + sb0, gBl0 + (size_t)k0 * N);  cp16(bl + sb1, gBl1 + (size_t)k0 * N);
        cp_commit();
    };
    auto COMP = [&](int buf, int kb) {
        const uint32_t aBaseH = sb + (buf * A_EL) * 2 + aOff;
        const uint32_t aBaseL = sb + (10240 + buf * A_EL) * 2 + aOff;
        const uint32_t bBaseH = sb + (20480 + buf * B_EL) * 2 + bOff;
        const uint32_t bBaseL = sb + (29184 + buf * B_EL) * 2 + bOff;
        uint32_t afh[4][4], afl[4][4], bfh[4][2], bfl[4][2];
        #pragma unroll
        for (int mt = 0; mt < 4; mt++) {
            ldmx4(aBaseH + ((mt * 16 * 40 + kb) << 1),
                  afh[mt][0], afh[mt][1], afh[mt][2], afh[mt][3]);
            ldmx4(aBaseL + ((mt * 16 * 40 + kb) << 1),
                  afl[mt][0], afl[mt][1], afl[mt][2], afl[mt][3]);
        }
        #pragma unroll
        for (int np = 0; np < 2; np++) {
            ldmx4t(bBaseH + ((kb * 136 + np * 16) << 1),
                   bfh[2*np][0], bfh[2*np][1], bfh[2*np+1][0], bfh[2*np+1][1]);
            ldmx4t(bBaseL + ((kb * 136 + np * 16) << 1),
                   bfl[2*np][0], bfl[2*np][1], bfl[2*np+1][0], bfl[2*np+1][1]);
        }
        #pragma unroll
        for (int mt = 0; mt < 4; mt++)
            #pragma unroll
            for (int nt = 0; nt < 4; nt++) {
                mma16816(acc[mt][nt], afh[mt], bfh[nt]);
                mma16816(acc[mt][nt], afh[mt], bfl[nt]);
                mma16816(acc[mt][nt], afl[mt], bfh[nt]);
            }
    };

    ISSUE(0, 0);
    const int iters = K / 32;
    for (int it = 0; it < iters; it++) {
        if (it + 1 < iters) { ISSUE((it + 1) * 32, (it + 1) & 1); cp_wait<1>(); }
        else                { cp_wait<0>(); }
        __syncthreads();
        COMP(it & 1, 0);
        COMP(it & 1, 16);
        __syncthreads();
    }

    // epilogue
    const int g = lane >> 2, tig = lane & 3;
    #pragma unroll
    for (int mt = 0; mt < 4; mt++) {
        #pragma unroll
        for (int nt = 0; nt < 4; nt++) {
            const int row = m0 + wm + mt * 16 + g;
            const int col = n0 + wn + nt * 8 + tig * 2;
            const float* a4 = acc[mt][nt];
            if (EPI == 3) {
                __nv_bfloat162 h01, l01, h23, l23;
                split2(a4[0], a4[1], h01, l01);
                split2(a4[2], a4[3], h23, l23);
                *(__nv_bfloat162*)(Ohi + (size_t)row * N + col)       = h01;
                *(__nv_bfloat162*)(Olo + (size_t)row * N + col)       = l01;
                *(__nv_bfloat162*)(Ohi + (size_t)(row + 8) * N + col) = h23;
                *(__nv_bfloat162*)(Olo + (size_t)(row + 8) * N + col) = l23;
            } else if (EPI == 1) {
                float b0 = bias[col], b1 = bias[col + 1];
                float v0 = fmaxf(a4[0] + b0, 0.f), v1 = fmaxf(a4[1] + b1, 0.f);
                float v2 = fmaxf(a4[2] + b0, 0.f), v3 = fmaxf(a4[3] + b1, 0.f);
                __nv_bfloat162 h01, l01, h23, l23;
                split2(v0, v1, h01, l01);
                split2(v2, v3, h23, l23);
                *(__nv_bfloat162*)(Ohi + (size_t)row * N + col)       = h01;
                *(__nv_bfloat162*)(Olo + (size_t)row * N + col)       = l01;
                *(__nv_bfloat162*)(Ohi + (size_t)(row + 8) * N + col) = h23;
                *(__nv_bfloat162*)(Olo + (size_t)(row + 8) * N + col) = l23;
            } else { // EPI == 2
                float b0 = bias[col], b1 = bias[col + 1];
                float2 ad0 = *(const float2*)(addm + (size_t)row * N + col);
                float2 ad1 = *(const float2*)(addm + (size_t)(row + 8) * N + col);
                *(float2*)(C + (size_t)row * N + col) =
                    make_float2(a4[0] + b0 + ad0.x, a4[1] + b1 + ad0.y);
                *(float2*)(C + (size_t)(row + 8) * N + col) =
                    make_float2(a4[2] + b0 + ad1.x, a4[3] + b1 + ad1.y);
            }
        }
    }
}

// -----------------------------------------------------------------------------
// Fused attention scores + softmax.
// grid = (Sq/32, NBH), 256 threads. Block: 32 query rows x all 1024 keys.
// Scores staged in smem fp32 [32][1032]; K tiles double-buffered via cp.async.
// Dynamic smem bytes:
//   sS   @ 0        : 32*1032*4 = 132096
//   sQh  @ 132096   : 32*72*2   = 4608
//   sQl  @ 136704   : 4608
//   sKh0 @ 141312, sKh1 @ 159744 : 128*72*2 = 18432 each
//   sKl0 @ 178176, sKl1 @ 196608
//   total 215040
// -----------------------------------------------------------------------------
#define FS_S    0u
#define FS_QH   132096u
#define FS_QL   136704u
#define FS_KH0  141312u
#define FS_KL0  178176u
#define FS_KBUF 18432u
#define FS_SMEM 215040u
#define SSTRIDE 1032

__global__ __launch_bounds__(256) void scores_softmax(
    const __nv_bfloat16* __restrict__ Qh, const __nv_bfloat16* __restrict__ Ql,
    const __nv_bfloat16* __restrict__ Kh, const __nv_bfloat16* __restrict__ Kl,
    float* __restrict__ attn)
{
    extern __shared__ __align__(16) char dsm[];
    const uint32_t sbase = smem_u32(dsm);
    float* sS = (float*)dsm;

    const int tid = threadIdx.x;
    const int lane = tid & 31;
    const int wid = tid >> 5;
    const int bh = blockIdx.y;
    const int m0 = blockIdx.x * 32;
    const size_t off = (size_t)(bh >> 5) * ((size_t)Sq * Dd) + (size_t)(bh & 31) * HDh;

    // ---- issue Q (group together with K chunk 0) ----
    {
        int row = tid >> 3, col = (tid & 7) * 8;
        uint32_t d = (row * 72 + col) * 2;
        cp16(sbase + FS_QH + d, Qh + off + (size_t)(m0 + row) * Dd + col);
        cp16(sbase + FS_QL + d, Ql + off + (size_t)(m0 + row) * Dd + col);
    }
    auto ISSUEK = [&](int chunk, int buf) {
        #pragma unroll
        for (int p = 0; p < 4; p++) {
            int idx = tid + p * 256;
            int row = idx >> 3, col = (idx & 7) * 8;
            uint32_t d = (row * 72 + col) * 2 + buf * FS_KBUF;
            const size_t gsrc = off + (size_t)(chunk * 128 + row) * Dd + col;
            cp16(sbase + FS_KH0 + d, Kh + gsrc);
            cp16(sbase + FS_KL0 + d, Kl + gsrc);
        }
        cp_commit();
    };
    ISSUEK(0, 0);   // commits Q + K0 as group 0

    const int wm = (wid & 1) * 16;        // query-row offset within 32
    const int wn = (wid >> 1) * 32;       // key-col offset within 128-chunk
    const uint32_t aOff = ((wm + (lane & 15)) * 72 + ((lane >> 4) << 3)) * 2;
    const int bRow = ((lane >> 4) << 3) + (lane & 7);
    const int bKof = ((lane >> 3) & 1) << 3;
    const uint32_t bOff = ((wn + bRow) * 72 + bKof) * 2;

    uint32_t afh[4][4], afl[4][4];        // Q fragments for 4 k-steps

    for (int it = 0; it < 8; it++) {
        if (it < 7) { ISSUEK(it + 1, (it + 1) & 1); cp_wait<1>(); }
        else        { cp_wait<0>(); }
        __syncthreads();

        if (it == 0) {
            #pragma unroll
            for (int kb4 = 0; kb4 < 4; kb4++) {
                ldmx4(sbase + FS_QH + aOff + ((kb4 * 16) << 1),
                      afh[kb4][0], afh[kb4][1], afh[kb4][2], afh[kb4][3]);
                ldmx4(sbase + FS_QL + aOff + ((kb4 * 16) << 1),
                      afl[kb4][0], afl[kb4][1], afl[kb4][2], afl[kb4][3]);
            }
        }

        const uint32_t kh = sbase + FS_KH0 + (it & 1) * FS_KBUF + bOff;
        const uint32_t kl = sbase + FS_KL0 + (it & 1) * FS_KBUF + bOff;

        float acc[4][4];
        #pragma unroll
        for (int nt = 0; nt < 4; nt++)
            #pragma unroll
            for (int t = 0; t < 4; t++) acc[nt][t] = 0.f;

        #pragma unroll
        for (int kb4 = 0; kb4 < 4; kb4++) {
            uint32_t bfh[4][2], bfl[4][2];
            #pragma unroll
            for (int np = 0; np < 2; np++) {
                ldmx4(kh + ((np * 16 * 72 + kb4 * 16) << 1),
                      bfh[2*np][0], bfh[2*np][1], bfh[2*np+1][0], bfh[2*np+1][1]);
                ldmx4(kl + ((np * 16 * 72 + kb4 * 16) << 1),
                      bfl[2*np][0], bfl[2*np][1], bfl[2*np+1][0], bfl[2*np+1][1]);
            }
            #pragma unroll
            for (int nt = 0; nt < 4; nt++) {
                mma16816(acc[nt], afh[kb4], bfh[nt]);
                mma16816(acc[nt], afh[kb4], bfl[nt]);
                mma16816(acc[nt], afl[kb4], bfh[nt]);
            }
        }

        // stage scores to smem
        const int g = lane >> 2, tig = lane & 3;
        #pragma unroll
        for (int nt = 0; nt < 4; nt++) {
            const int col = it * 128 + wn + nt * 8 + tig * 2;
            *(float2*)(sS + (wm + g) * SSTRIDE + col)     = make_float2(acc[nt][0], acc[nt][1]);
            *(float2*)(sS + (wm + g + 8) * SSTRIDE + col) = make_float2(acc[nt][2], acc[nt][3]);
        }
        __syncthreads();
    }

    // ---- softmax from smem, write probs to global ----
    const float c = INV_SQRT_D;
    #pragma unroll
    for (int rr = 0; rr < 4; rr++) {
        const int row = wid * 4 + rr;
        const float4* sr = (const float4*)(sS + row * SSTRIDE);
        float4 v[8];
        float mx = -1e30f;
        #pragma unroll
        for (int j = 0; j < 8; j++) {
            v[j] = sr[lane + j * 32];
            v[j].x *= c; v[j].y *= c; v[j].z *= c; v[j].w *= c;
            mx = fmaxf(mx, fmaxf(fmaxf(v[j].x, v[j].y), fmaxf(v[j].z, v[j].w)));
        }
        #pragma unroll
        for (int o = 16; o; o >>= 1) mx = fmaxf(mx, __shfl_xor_sync(0xffffffffu, mx, o));
        float sm = 0.f;
        #pragma unroll
        for (int j = 0; j < 8; j++) {
            v[j].x = __expf(v[j].x - mx); v[j].y = __expf(v[j].y - mx);
            v[j].z = __expf(v[j].z - mx); v[j].w = __expf(v[j].w - mx);
            sm += v[j].x + v[j].y + v[j].z + v[j].w;
        }
        #pragma unroll
        for (int o = 16; o; o >>= 1) sm += __shfl_xor_sync(0xffffffffu, sm, o);
        const float inv = __fdividef(1.0f, sm);
        float4* orow = (float4*)(attn + (size_t)bh * Sq * Sq + (size_t)(m0 + row) * Sq);
        #pragma unroll
        for (int j = 0; j < 8; j++) {
            v[j].x *= inv; v[j].y *= inv; v[j].z *= inv; v[j].w *= inv;
            orow[lane + j * 32] = v[j];
        }
    }
}

// -----------------------------------------------------------------------------
extern "C" void kernel_launch(void* const* d_in, const int* in_sizes, int n_in,
                              void* d_out, int out_size)
{
    (void)in_sizes; (void)n_in; (void)out_size;
    const float* x    = (const float*)d_in[0];
    const float* Wq   = (const float*)d_in[1];
    const float* Wk   = (const float*)d_in[2];
    /* d_in[3] = Wv : dead in the reference */
    const float* ln1s = (const float*)d_in[4];
    const float* ln1b = (const float*)d_in[5];
    const float* ln2s = (const float*)d_in[6];
    const float* ln2b = (const float*)d_in[7];
    const float* ff1w = (const float*)d_in[8];
    const float* ff1b = (const float*)d_in[9];
    const float* ff2w = (const float*)d_in[10];
    const float* ff2b = (const float*)d_in[11];

    float* out  = (float*)d_out;
    float* attn = out + (size_t)NTOK * Dd;

    float* px2;
    __nv_bfloat16 *phh, *phl, *ph2h, *ph2l, *pf1h, *pf1l, *pqh, *pql, *pkh, *pkl;
    __nv_bfloat16 *pwqh, *pwql, *pwkh, *pwkl, *pw1h, *pw1l, *pw2h, *pw2l;
    cudaGetSymbolAddress((void**)&px2,  g_x2);
    cudaGetSymbolAddress((void**)&phh,  g_hh);
    cudaGetSymbolAddress((void**)&phl,  g_hl);
    cudaGetSymbolAddress((void**)&ph2h, g_h2h);
    cudaGetSymbolAddress((void**)&ph2l, g_h2l);
    cudaGetSymbolAddress((void**)&pf1h, g_f1h);
    cudaGetSymbolAddress((void**)&pf1l, g_f1l);
    cudaGetSymbolAddress((void**)&pqh,  g_qh);
    cudaGetSymbolAddress((void**)&pql,  g_ql);
    cudaGetSymbolAddress((void**)&pkh,  g_kh);
    cudaGetSymbolAddress((void**)&pkl,  g_kl);
    cudaGetSymbolAddress((void**)&pwqh, g_wqh);
    cudaGetSymbolAddress((void**)&pwql, g_wql);
    cudaGetSymbolAddress((void**)&pwkh, g_wkh);
    cudaGetSymbolAddress((void**)&pwkl, g_wkl);
    cudaGetSymbolAddress((void**)&pw1h, g_w1h);
    cudaGetSymbolAddress((void**)&pw1l, g_w1l);
    cudaGetSymbolAddress((void**)&pw2h, g_w2h);
    cudaGetSymbolAddress((void**)&pw2l, g_w2l);

    cudaFuncSetAttribute(gemm3<1>, cudaFuncAttributeMaxDynamicSharedMemorySize, GEMM_SMEM);
    cudaFuncSetAttribute(gemm3<2>, cudaFuncAttributeMaxDynamicSharedMemorySize, GEMM_SMEM);
    cudaFuncSetAttribute(gemm3<3>, cudaFuncAttributeMaxDynamicSharedMemorySize, GEMM_SMEM);
    cudaFuncSetAttribute(scores_softmax, cudaFuncAttributeMaxDynamicSharedMemorySize, FS_SMEM);

    const int n4 = Dd * Dd / 4;
    splitf<<<(n4 + 255) / 256, 256>>>((const float4*)Wq,   pwqh, pwql, n4);
    splitf<<<(n4 + 255) / 256, 256>>>((const float4*)Wk,   pwkh, pwkl, n4);
    splitf<<<(n4 + 255) / 256, 256>>>((const float4*)ff1w, pw1h, pw1l, n4);
    splitf<<<(n4 + 255) / 256, 256>>>((const float4*)ff2w, pw2h, pw2l, n4);

    ln_fused<<<NTOK, 256>>>(x, ln1s, ln1b, ln2s, ln2b);

    dim3 g0(Dd / 128, NTOK / 128);
    gemm3<3><<<g0, 256, GEMM_SMEM>>>(NTOK, Dd, Dd, phh, phl, pwqh, pwql,
                                     nullptr, nullptr, nullptr, pqh, pql);
    gemm3<3><<<g0, 256, GEMM_SMEM>>>(NTOK, Dd, Dd, phh, phl, pwkh, pwkl,
                                     nullptr, nullptr, nullptr, pkh, pkl);
    gemm3<1><<<g0, 256, GEMM_SMEM>>>(NTOK, Dd, Dd, ph2h, ph2l, pw1h, pw1l,
                                     nullptr, ff1b, nullptr, pf1h, pf1l);
    gemm3<2><<<g0, 256, GEMM_SMEM>>>(NTOK, Dd, Dd, pf1h, pf1l, pw2h, pw2l,
                                     out, ff2b, px2, nullptr, nullptr);

    dim3 gs(Sq / 32, NBH);
    scores_softmax<<<gs, 256, FS_SMEM>>>(pqh, pql, pkh, pkl, attn);
}

// round 4
// speedup vs baseline: 1.0633x; 1.0633x over previous
#include <cuda_runtime.h>
#include <cuda_bf16.h>
#include <cstdint>
#include <math.h>

#define Dd    2048
#define NTOK  4096
#define Sq    1024
#define HDh   64
#define NBH   128
#define EPSV  1e-5f
#define INV_SQRT_D 0.022097086912079608f

// ---------------- scratch ---------------------------------------------------
__device__ float g_x2[(size_t)NTOK * Dd];
__device__ __nv_bfloat16 g_hh [(size_t)NTOK * Dd], g_hl [(size_t)NTOK * Dd];
__device__ __nv_bfloat16 g_h2h[(size_t)NTOK * Dd], g_h2l[(size_t)NTOK * Dd];
__device__ __nv_bfloat16 g_f1h[(size_t)NTOK * Dd], g_f1l[(size_t)NTOK * Dd];
__device__ __nv_bfloat16 g_qh [(size_t)NTOK * Dd], g_ql [(size_t)NTOK * Dd];
__device__ __nv_bfloat16 g_kh [(size_t)NTOK * Dd], g_kl [(size_t)NTOK * Dd];
__device__ __nv_bfloat16 g_wqh[(size_t)Dd * Dd], g_wql[(size_t)Dd * Dd];
__device__ __nv_bfloat16 g_wkh[(size_t)Dd * Dd], g_wkl[(size_t)Dd * Dd];
__device__ __nv_bfloat16 g_w1h[(size_t)Dd * Dd], g_w1l[(size_t)Dd * Dd];
__device__ __nv_bfloat16 g_w2h[(size_t)Dd * Dd], g_w2l[(size_t)Dd * Dd];

// ---------------- helpers ----------------------------------------------------
__device__ __forceinline__ uint32_t smem_u32(const void* p) {
    return (uint32_t)__cvta_generic_to_shared(p);
}
__device__ __forceinline__ void cp16(uint32_t dst, const void* src) {
    asm volatile("cp.async.cg.shared.global [%0], [%1], 16;" :: "r"(dst), "l"(src));
}
__device__ __forceinline__ void cp_commit() {
    asm volatile("cp.async.commit_group;");
}
template<int N> __device__ __forceinline__ void cp_wait() {
    asm volatile("cp.async.wait_group %0;" :: "n"(N));
}
__device__ __forceinline__ void ldmx4(uint32_t a, uint32_t& r0, uint32_t& r1,
                                      uint32_t& r2, uint32_t& r3) {
    asm volatile("ldmatrix.sync.aligned.m8n8.x4.shared.b16 {%0,%1,%2,%3},[%4];"
                 : "=r"(r0), "=r"(r1), "=r"(r2), "=r"(r3) : "r"(a));
}
__device__ __forceinline__ void ldmx4t(uint32_t a, uint32_t& r0, uint32_t& r1,
                                       uint32_t& r2, uint32_t& r3) {
    asm volatile("ldmatrix.sync.aligned.m8n8.x4.trans.shared.b16 {%0,%1,%2,%3},[%4];"
                 : "=r"(r0), "=r"(r1), "=r"(r2), "=r"(r3) : "r"(a));
}
__device__ __forceinline__ void mma16816(float* c, const uint32_t* a, const uint32_t* b) {
    asm volatile(
        "mma.sync.aligned.m16n8k16.row.col.f32.bf16.bf16.f32 "
        "{%0,%1,%2,%3},{%4,%5,%6,%7},{%8,%9},{%0,%1,%2,%3};"
        : "+f"(c[0]), "+f"(c[1]), "+f"(c[2]), "+f"(c[3])
        : "r"(a[0]), "r"(a[1]), "r"(a[2]), "r"(a[3]), "r"(b[0]), "r"(b[1]));
}
__device__ __forceinline__ void split2(float v0, float v1,
                                       __nv_bfloat162& hi, __nv_bfloat162& lo) {
    __nv_bfloat16 h0 = __float2bfloat16(v0);
    __nv_bfloat16 h1 = __float2bfloat16(v1);
    __nv_bfloat16 l0 = __float2bfloat16(v0 - __bfloat162float(h0));
    __nv_bfloat16 l1 = __float2bfloat16(v1 - __bfloat162float(h1));
    hi.x = h0; hi.y = h1; lo.x = l0; lo.y = l1;
}
__device__ __forceinline__ void split_store4(__nv_bfloat16* hi, __nv_bfloat16* lo,
                                             size_t idx, float4 v) {
    __nv_bfloat162 h01, l01, h23, l23;
    split2(v.x, v.y, h01, l01);
    split2(v.z, v.w, h23, l23);
    *(__nv_bfloat162*)(hi + idx)     = h01;
    *(__nv_bfloat162*)(hi + idx + 2) = h23;
    *(__nv_bfloat162*)(lo + idx)     = l01;
    *(__nv_bfloat162*)(lo + idx + 2) = l23;
}

// ---------------- weight split ----------------------------------------------
__global__ __launch_bounds__(256) void splitf(const float4* __restrict__ W,
                                              __nv_bfloat16* __restrict__ hi,
                                              __nv_bfloat16* __restrict__ lo, int n4) {
    int i = blockIdx.x * 256 + threadIdx.x;
    if (i >= n4) return;
    split_store4(hi, lo, (size_t)i * 4, W[i]);
}

// ---------------- fused LN1 / residual / LN2 ---------------------------------
__global__ __launch_bounds__(256) void ln_fused(
    const float* __restrict__ x,
    const float* __restrict__ s1, const float* __restrict__ b1,
    const float* __restrict__ s2, const float* __restrict__ b2)
{
    __shared__ float rbuf[16];
    __shared__ float stats[2];
    const int tid = threadIdx.x;
    const size_t base = (size_t)blockIdx.x * Dd;
    const float4* xr = (const float4*)(x + base);
    float4 a0 = xr[tid];
    float4 a1 = xr[tid + 256];

    float s = a0.x + a0.y + a0.z + a0.w + a1.x + a1.y + a1.z + a1.w;
    float q = a0.x*a0.x + a0.y*a0.y + a0.z*a0.z + a0.w*a0.w
            + a1.x*a1.x + a1.y*a1.y + a1.z*a1.z + a1.w*a1.w;
    #pragma unroll
    for (int o = 16; o; o >>= 1) {
        s += __shfl_xor_sync(0xffffffffu, s, o);
        q += __shfl_xor_sync(0xffffffffu, q, o);
    }
    if ((tid & 31) == 0) { rbuf[tid >> 5] = s; rbuf[8 + (tid >> 5)] = q; }
    __syncthreads();
    if (tid == 0) {
        float ss = 0.f, qq = 0.f;
        #pragma unroll
        for (int i = 0; i < 8; i++) { ss += rbuf[i]; qq += rbuf[8 + i]; }
        float m = ss * (1.0f / Dd);
        stats[0] = m;
        stats[1] = rsqrtf(qq * (1.0f / Dd) - m * m + EPSV);
    }
    __syncthreads();
    float m = stats[0], r = stats[1];

    const float4* s1v = (const float4*)s1;
    const float4* b1v = (const float4*)b1;
    float4 sc0 = s1v[tid], sc1 = s1v[tid + 256];
    float4 bi0 = b1v[tid], bi1 = b1v[tid + 256];

    float4 h0, h1, x20, x21;
    h0.x = (a0.x - m) * r * sc0.x + bi0.x;  h0.y = (a0.y - m) * r * sc0.y + bi0.y;
    h0.z = (a0.z - m) * r * sc0.z + bi0.z;  h0.w = (a0.w - m) * r * sc0.w + bi0.w;
    h1.x = (a1.x - m) * r * sc1.x + bi1.x;  h1.y = (a1.y - m) * r * sc1.y + bi1.y;
    h1.z = (a1.z - m) * r * sc1.z + bi1.z;  h1.w = (a1.w - m) * r * sc1.w + bi1.w;
    x20.x = h0.x + a0.x; x20.y = h0.y + a0.y; x20.z = h0.z + a0.z; x20.w = h0.w + a0.w;
    x21.x = h1.x + a1.x; x21.y = h1.y + a1.y; x21.z = h1.z + a1.z; x21.w = h1.w + a1.w;

    split_store4(g_hh, g_hl, base + (size_t)tid * 4, h0);
    split_store4(g_hh, g_hl, base + (size_t)(tid + 256) * 4, h1);
    ((float4*)(g_x2 + base))[tid]       = x20;
    ((float4*)(g_x2 + base))[tid + 256] = x21;

    s = x20.x + x20.y + x20.z + x20.w + x21.x + x21.y + x21.z + x21.w;
    q = x20.x*x20.x + x20.y*x20.y + x20.z*x20.z + x20.w*x20.w
      + x21.x*x21.x + x21.y*x21.y + x21.z*x21.z + x21.w*x21.w;
    #pragma unroll
    for (int o = 16; o; o >>= 1) {
        s += __shfl_xor_sync(0xffffffffu, s, o);
        q += __shfl_xor_sync(0xffffffffu, q, o);
    }
    if ((tid & 31) == 0) { rbuf[tid >> 5] = s; rbuf[8 + (tid >> 5)] = q; }
    __syncthreads();
    if (tid == 0) {
        float ss = 0.f, qq = 0.f;
        #pragma unroll
        for (int i = 0; i < 8; i++) { ss += rbuf[i]; qq += rbuf[8 + i]; }
        float mm = ss * (1.0f / Dd);
        stats[0] = mm;
        stats[1] = rsqrtf(qq * (1.0f / Dd) - mm * mm + EPSV);
    }
    __syncthreads();
    m = stats[0]; r = stats[1];

    const float4* s2v = (const float4*)s2;
    const float4* b2v = (const float4*)b2;
    sc0 = s2v[tid]; sc1 = s2v[tid + 256];
    bi0 = b2v[tid]; bi1 = b2v[tid + 256];
    float4 o0, o1;
    o0.x = (x20.x - m) * r * sc0.x + bi0.x;  o0.y = (x20.y - m) * r * sc0.y + bi0.y;
    o0.z = (x20.z - m) * r * sc0.z + bi0.z;  o0.w = (x20.w - m) * r * sc0.w + bi0.w;
    o1.x = (x21.x - m) * r * sc1.x + bi1.x;  o1.y = (x21.y - m) * r * sc1.y + bi1.y;
    o1.z = (x21.z - m) * r * sc1.z + bi1.z;  o1.w = (x21.w - m) * r * sc1.w + bi1.w;
    split_store4(g_h2h, g_h2l, base + (size_t)tid * 4, o0);
    split_store4(g_h2h, g_h2l, base + (size_t)(tid + 256) * 4, o1);
}

// ---------------------------------------------------------------------------
// bf16 split-3 GEMM (R2 register-pipelined version — proven fastest).
// Block 128x128, BK=32, 256 threads = 8 warps (2Mx4N), warp tile 64x32.
// ---------------------------------------------------------------------------
template<int EPI>
__global__ __launch_bounds__(256) void gemm3(
    int M, int N, int K,
    const __nv_bfloat16* __restrict__ Ah, const __nv_bfloat16* __restrict__ Al,
    const __nv_bfloat16* __restrict__ Bh, const __nv_bfloat16* __restrict__ Bl,
    float* __restrict__ C,
    const float* __restrict__ bias, const float* __restrict__ addm,
    __nv_bfloat16* __restrict__ Ohi, __nv_bfloat16* __restrict__ Olo)
{
    __shared__ __nv_bfloat16 sAh[128 * 40], sAl[128 * 40];
    __shared__ __nv_bfloat16 sBh[32 * 136], sBl[32 * 136];

    const int tid = threadIdx.x;
    const int m0 = blockIdx.y * 128, n0 = blockIdx.x * 128;
    const int s0 = tid, s1 = tid + 256;

    const __nv_bfloat16* gAh0 = Ah + (size_t)(m0 + (s0 >> 2)) * K + (s0 & 3) * 8;
    const __nv_bfloat16* gAh1 = Ah + (size_t)(m0 + (s1 >> 2)) * K + (s1 & 3) * 8;
    const __nv_bfloat16* gAl0 = Al + (size_t)(m0 + (s0 >> 2)) * K + (s0 & 3) * 8;
    const __nv_bfloat16* gAl1 = Al + (size_t)(m0 + (s1 >> 2)) * K + (s1 & 3) * 8;
    const __nv_bfloat16* gBh0 = Bh + (size_t)(s0 >> 4) * N + n0 + (s0 & 15) * 8;
    const __nv_bfloat16* gBh1 = Bh + (size_t)(s1 >> 4) * N + n0 + (s1 & 15) * 8;
    const __nv_bfloat16* gBl0 = Bl + (size_t)(s0 >> 4) * N + n0 + (s0 & 15) * 8;
    const __nv_bfloat16* gBl1 = Bl + (size_t)(s1 >> 4) * N + n0 + (s1 & 15) * 8;

    const int sa0 = (s0 >> 2) * 40 + (s0 & 3) * 8;
    const int sa1 = (s1 >> 2) * 40 + (s1 & 3) * 8;
    const int sb0 = (s0 >> 4) * 136 + (s0 & 15) * 8;
    const int sb1 = (s1 >> 4) * 136 + (s1 & 15) * 8;

    const int lane = tid & 31;
    const int wid = tid >> 5;
    const int wm = (wid & 1) * 64;
    const int wn = (wid >> 1) * 32;

    const uint32_t aBaseH = smem_u32(sAh) + (((wm + (lane & 15)) * 40 + ((lane >> 4) << 3)) << 1);
    const uint32_t aBaseL = smem_u32(sAl) + (((wm + (lane & 15)) * 40 + ((lane >> 4) << 3)) << 1);
    const uint32_t bBaseH = smem_u32(sBh) + ((((lane & 15)) * 136 + wn + ((lane >> 4) << 3)) << 1);
    const uint32_t bBaseL = smem_u32(sBl) + ((((lane & 15)) * 136 + wn + ((lane >> 4) << 3)) << 1);

    float acc[4][4][4];
    #pragma unroll
    for (int i = 0; i < 4; i++)
        #pragma unroll
        for (int j = 0; j < 4; j++)
            #pragma unroll
            for (int t = 0; t < 4; t++) acc[i][j][t] = 0.f;

    uint4 vah0, vah1, val0, val1, vbh0, vbh1, vbl0, vbl1;

    auto LDG = [&](int k0) {
        vah0 = *(const uint4*)(gAh0 + k0);
        vah1 = *(const uint4*)(gAh1 + k0);
        val0 = *(const uint4*)(gAl0 + k0);
        val1 = *(const uint4*)(gAl1 + k0);
        vbh0 = *(const uint4*)(gBh0 + (size_t)k0 * N);
        vbh1 = *(const uint4*)(gBh1 + (size_t)k0 * N);
        vbl0 = *(const uint4*)(gBl0 + (size_t)k0 * N);
        vbl1 = *(const uint4*)(gBl1 + (size_t)k0 * N);
    };
    auto STS = [&]() {
        *(uint4*)(sAh + sa0) = vah0;  *(uint4*)(sAh + sa1) = vah1;
        *(uint4*)(sAl + sa0) = val0;  *(uint4*)(sAl + sa1) = val1;
        *(uint4*)(sBh + sb0) = vbh0;  *(uint4*)(sBh + sb1) = vbh1;
        *(uint4*)(sBl + sb0) = vbl0;  *(uint4*)(sBl + sb1) = vbl1;
    };
    auto COMP = [&](int kb) {
        uint32_t afh[4][4], afl[4][4], bfh[4][2], bfl[4][2];
        #pragma unroll
        for (int mt = 0; mt < 4; mt++) {
            ldmx4(aBaseH + ((mt * 16 * 40 + kb) << 1),
                  afh[mt][0], afh[mt][1], afh[mt][2], afh[mt][3]);
            ldmx4(aBaseL + ((mt * 16 * 40 + kb) << 1),
                  afl[mt][0], afl[mt][1], afl[mt][2], afl[mt][3]);
        }
        #pragma unroll
        for (int np = 0; np < 2; np++) {
            ldmx4t(bBaseH + ((kb * 136 + np * 16) << 1),
                   bfh[2*np][0], bfh[2*np][1], bfh[2*np+1][0], bfh[2*np+1][1]);
            ldmx4t(bBaseL + ((kb * 136 + np * 16) << 1),
                   bfl[2*np][0], bfl[2*np][1], bfl[2*np+1][0], bfl[2*np+1][1]);
        }
        #pragma unroll
        for (int mt = 0; mt < 4; mt++)
            #pragma unroll
            for (int nt = 0; nt < 4; nt++) {
                mma16816(acc[mt][nt], afh[mt], bfh[nt]);
                mma16816(acc[mt][nt], afh[mt], bfl[nt]);
                mma16816(acc[mt][nt], afl[mt], bfh[nt]);
            }
    };

    LDG(0);
    STS();
    __syncthreads();
    for (int k0 = 32; k0 < K; k0 += 32) {
        LDG(k0);
        COMP(0);
        COMP(16);
        __syncthreads();
        STS();
        __syncthreads();
    }
    COMP(0);
    COMP(16);

    const int g = lane >> 2, tig = lane & 3;
    #pragma unroll
    for (int mt = 0; mt < 4; mt++) {
        #pragma unroll
        for (int nt = 0; nt < 4; nt++) {
            const int row = m0 + wm + mt * 16 + g;
            const int col = n0 + wn + nt * 8 + tig * 2;
            const float* a4 = acc[mt][nt];
            if (EPI == 3) {
                __nv_bfloat162 h01, l01, h23, l23;
                split2(a4[0], a4[1], h01, l01);
                split2(a4[2], a4[3], h23, l23);
                *(__nv_bfloat162*)(Ohi + (size_t)row * N + col)       = h01;
                *(__nv_bfloat162*)(Olo + (size_t)row * N + col)       = l01;
                *(__nv_bfloat162*)(Ohi + (size_t)(row + 8) * N + col) = h23;
                *(__nv_bfloat162*)(Olo + (size_t)(row + 8) * N + col) = l23;
            } else if (EPI == 1) {
                float b0 = bias[col], b1 = bias[col + 1];
                float v0 = fmaxf(a4[0] + b0, 0.f), v1 = fmaxf(a4[1] + b1, 0.f);
                float v2 = fmaxf(a4[2] + b0, 0.f), v3 = fmaxf(a4[3] + b1, 0.f);
                __nv_bfloat162 h01, l01, h23, l23;
                split2(v0, v1, h01, l01);
                split2(v2, v3, h23, l23);
                *(__nv_bfloat162*)(Ohi + (size_t)row * N + col)       = h01;
                *(__nv_bfloat162*)(Olo + (size_t)row * N + col)       = l01;
                *(__nv_bfloat162*)(Ohi + (size_t)(row + 8) * N + col) = h23;
                *(__nv_bfloat162*)(Olo + (size_t)(row + 8) * N + col) = l23;
            } else { // EPI == 2
                float b0 = bias[col], b1 = bias[col + 1];
                float2 ad0 = *(const float2*)(addm + (size_t)row * N + col);
                float2 ad1 = *(const float2*)(addm + (size_t)(row + 8) * N + col);
                *(float2*)(C + (size_t)row * N + col) =
                    make_float2(a4[0] + b0 + ad0.x, a4[1] + b1 + ad0.y);
                *(float2*)(C + (size_t)(row + 8) * N + col) =
                    make_float2(a4[2] + b0 + ad1.x, a4[3] + b1 + ad1.y);
            }
        }
    }
}

// -----------------------------------------------------------------------------
// Fused scores + softmax, register-resident scores.
// grid = (Sq/16, NBH), 512 threads = 16 warps. Each block: 16 q-rows x 1024 keys.
// Warp w covers keys [chunk*256 + w*16, +16); 4 chunks of 256 keys, cp.async
// double-buffered. Each thread holds 32 score floats (4 chunks x 2 nt x 4).
// smem: Qh@0(2304) Ql@2304 | K bufs: hi/lo 36864 each, stride 73728 | red@152064
// -----------------------------------------------------------------------------
#define FS_QH   0u
#define FS_QL   2304u
#define FS_KH0  4608u
#define FS_KL0  41472u
#define FS_KSTR 73728u
#define FS_RED  152064u
#define FS_SMEM 153088u

__global__ __launch_bounds__(512) void scores_softmax(
    const __nv_bfloat16* __restrict__ Qh, const __nv_bfloat16* __restrict__ Ql,
    const __nv_bfloat16* __restrict__ Kh, const __nv_bfloat16* __restrict__ Kl,
    float* __restrict__ attn)
{
    extern __shared__ __align__(16) char dsm[];
    const uint32_t sbase = smem_u32(dsm);
    float* red = (float*)(dsm + FS_RED);   // [16 rows][16 warps]

    const int tid = threadIdx.x;
    const int lane = tid & 31;
    const int wid = tid >> 5;
    const int bh = blockIdx.y;
    const int m0 = blockIdx.x * 16;
    const size_t off = (size_t)(bh >> 5) * ((size_t)Sq * Dd) + (size_t)(bh & 31) * HDh;

    // Q issue (grouped with K chunk 0)
    if (tid < 256) {
        int plane = tid >> 7, i2 = tid & 127;
        int row = i2 >> 3, col = (i2 & 7) * 8;
        const __nv_bfloat16* src = (plane ? Ql : Qh) + off + (size_t)(m0 + row) * Dd + col;
        cp16(sbase + (plane ? FS_QL : FS_QH) + (row * 72 + col) * 2, src);
    }
    auto ISSUEK = [&](int chunk, int buf) {
        #pragma unroll
        for (int p = 0; p < 8; p++) {
            int idx = tid + p * 512;                 // 0..4095
            int plane = idx >> 11;
            int i2 = idx & 2047;
            int row = i2 >> 3, col = (i2 & 7) * 8;
            const __nv_bfloat16* src = (plane ? Kl : Kh) + off
                                     + (size_t)(chunk * 256 + row) * Dd + col;
            cp16(sbase + (plane ? FS_KL0 : FS_KH0) + (uint32_t)buf * FS_KSTR
                 + (row * 72 + col) * 2, src);
        }
        cp_commit();
    };
    ISSUEK(0, 0);           // group 0 (Q + K0)
    ISSUEK(1, 1);           // group 1
    cp_wait<1>();           // group 0 done
    __syncthreads();

    // Q fragments (rows 0-15, 4 k-steps, hi/lo)
    const uint32_t aOff = (((lane & 15)) * 72 + ((lane >> 4) << 3)) * 2;
    uint32_t afh[4][4], afl[4][4];
    #pragma unroll
    for (int kb4 = 0; kb4 < 4; kb4++) {
        ldmx4(sbase + FS_QH + aOff + ((kb4 * 16) << 1),
              afh[kb4][0], afh[kb4][1], afh[kb4][2], afh[kb4][3]);
        ldmx4(sbase + FS_QL + aOff + ((kb4 * 16) << 1),
              afl[kb4][0], afl[kb4][1], afl[kb4][2], afl[kb4][3]);
    }

    const int bRow = ((lane >> 4) << 3) + (lane & 7);
    const int bKof = ((lane >> 3) & 1) << 3;
    const uint32_t bOff = ((wid * 16 + bRow) * 72 + bKof) * 2;

    float acc[4][2][4];
    #pragma unroll
    for (int it = 0; it < 4; it++)
        #pragma unroll
        for (int nt = 0; nt < 2; nt++)
            #pragma unroll
            for (int t = 0; t < 4; t++) acc[it][nt][t] = 0.f;

    #pragma unroll
    for (int it = 0; it < 4; it++) {
        const int buf = it & 1;
        const uint32_t kh = sbase + FS_KH0 + (uint32_t)buf * FS_KSTR + bOff;
        const uint32_t kl = sbase + FS_KL0 + (uint32_t)buf * FS_KSTR + bOff;
        #pragma unroll
        for (int kb4 = 0; kb4 < 4; kb4++) {
            uint32_t bh4[4], bl4[4];
            ldmx4(kh + ((kb4 * 16) << 1), bh4[0], bh4[1], bh4[2], bh4[3]);
            ldmx4(kl + ((kb4 * 16) << 1), bl4[0], bl4[1], bl4[2], bl4[3]);
            #pragma unroll
            for (int nt = 0; nt < 2; nt++) {
                mma16816(acc[it][nt], afh[kb4], &bh4[nt * 2]);
                mma16816(acc[it][nt], afh[kb4], &bl4[nt * 2]);
                mma16816(acc[it][nt], afl[kb4], &bh4[nt * 2]);
            }
        }
        if (it < 2) {
            __syncthreads();              // everyone done reading buf before refill
            ISSUEK(it + 2, buf);
            cp_wait<1>();                 // next chunk resident
            __syncthreads();
        } else if (it == 2) {
            cp_wait<0>();
            __syncthreads();
        }
    }

    // ---- softmax over register-resident scores ----
    const int g = lane >> 2, tig = lane & 3;
    const float c = INV_SQRT_D;
    float mx0 = -1e30f, mx1 = -1e30f;
    #pragma unroll
    for (int it = 0; it < 4; it++)
        #pragma unroll
        for (int nt = 0; nt < 2; nt++) {
            float* a4 = acc[it][nt];
            a4[0] *= c; a4[1] *= c; a4[2] *= c; a4[3] *= c;
            mx0 = fmaxf(mx0, fmaxf(a4[0], a4[1]));
            mx1 = fmaxf(mx1, fmaxf(a4[2], a4[3]));
        }
    mx0 = fmaxf(mx0, __shfl_xor_sync(0xffffffffu, mx0, 1));
    mx0 = fmaxf(mx0, __shfl_xor_sync(0xffffffffu, mx0, 2));
    mx1 = fmaxf(mx1, __shfl_xor_sync(0xffffffffu, mx1, 1));
    mx1 = fmaxf(mx1, __shfl_xor_sync(0xffffffffu, mx1, 2));
    if (tig == 0) { red[g * 16 + wid] = mx0; red[(g + 8) * 16 + wid] = mx1; }
    __syncthreads();
    float m0f = -1e30f, m1f = -1e30f;
    #pragma unroll
    for (int w = 0; w < 16; w++) {
        m0f = fmaxf(m0f, red[g * 16 + w]);
        m1f = fmaxf(m1f, red[(g + 8) * 16 + w]);
    }
    __syncthreads();   // before red reuse

    float s0 = 0.f, s1 = 0.f;
    #pragma unroll
    for (int it = 0; it < 4; it++)
        #pragma unroll
        for (int nt = 0; nt < 2; nt++) {
            float* a4 = acc[it][nt];
            a4[0] = __expf(a4[0] - m0f); a4[1] = __expf(a4[1] - m0f);
            a4[2] = __expf(a4[2] - m1f); a4[3] = __expf(a4[3] - m1f);
            s0 += a4[0] + a4[1];
            s1 += a4[2] + a4[3];
        }
    s0 += __shfl_xor_sync(0xffffffffu, s0, 1);
    s0 += __shfl_xor_sync(0xffffffffu, s0, 2);
    s1 += __shfl_xor_sync(0xffffffffu, s1, 1);
    s1 += __shfl_xor_sync(0xffffffffu, s1, 2);
    if (tig == 0) { red[g * 16 + wid] = s0; red[(g + 8) * 16 + wid] = s1; }
    __syncthreads();
    float t0 = 0.f, t1 = 0.f;
    #pragma unroll
    for (int w = 0; w < 16; w++) {
        t0 += red[g * 16 + w];
        t1 += red[(g + 8) * 16 + w];
    }
    const float inv0 = __fdividef(1.0f, t0);
    const float inv1 = __fdividef(1.0f, t1);

    float* base0 = attn + (size_t)bh * Sq * Sq + (size_t)(m0 + g) * Sq;
    float* base1 = base0 + (size_t)8 * Sq;
    #pragma unroll
    for (int it = 0; it < 4; it++)
        #pragma unroll
        for (int nt = 0; nt < 2; nt++) {
            const int col = it * 256 + wid * 16 + nt * 8 + tig * 2;
            const float* a4 = acc[it][nt];
            *(float2*)(base0 + col) = make_float2(a4[0] * inv0, a4[1] * inv0);
            *(float2*)(base1 + col) = make_float2(a4[2] * inv1, a4[3] * inv1);
        }
}

// -----------------------------------------------------------------------------
extern "C" void kernel_launch(void* const* d_in, const int* in_sizes, int n_in,
                              void* d_out, int out_size)
{
    (void)in_sizes; (void)n_in; (void)out_size;
    const float* x    = (const float*)d_in[0];
    const float* Wq   = (const float*)d_in[1];
    const float* Wk   = (const float*)d_in[2];
    /* d_in[3] = Wv : dead in the reference */
    const float* ln1s = (const float*)d_in[4];
    const float* ln1b = (const float*)d_in[5];
    const float* ln2s = (const float*)d_in[6];
    const float* ln2b = (const float*)d_in[7];
    const float* ff1w = (const float*)d_in[8];
    const float* ff1b = (const float*)d_in[9];
    const float* ff2w = (const float*)d_in[10];
    const float* ff2b = (const float*)d_in[11];

    float* out  = (float*)d_out;
    float* attn = out + (size_t)NTOK * Dd;

    float* px2;
    __nv_bfloat16 *phh, *phl, *ph2h, *ph2l, *pf1h, *pf1l, *pqh, *pql, *pkh, *pkl;
    __nv_bfloat16 *pwqh, *pwql, *pwkh, *pwkl, *pw1h, *pw1l, *pw2h, *pw2l;
    cudaGetSymbolAddress((void**)&px2,  g_x2);
    cudaGetSymbolAddress((void**)&phh,  g_hh);
    cudaGetSymbolAddress((void**)&phl,  g_hl);
    cudaGetSymbolAddress((void**)&ph2h, g_h2h);
    cudaGetSymbolAddress((void**)&ph2l, g_h2l);
    cudaGetSymbolAddress((void**)&pf1h, g_f1h);
    cudaGetSymbolAddress((void**)&pf1l, g_f1l);
    cudaGetSymbolAddress((void**)&pqh,  g_qh);
    cudaGetSymbolAddress((void**)&pql,  g_ql);
    cudaGetSymbolAddress((void**)&pkh,  g_kh);
    cudaGetSymbolAddress((void**)&pkl,  g_kl);
    cudaGetSymbolAddress((void**)&pwqh, g_wqh);
    cudaGetSymbolAddress((void**)&pwql, g_wql);
    cudaGetSymbolAddress((void**)&pwkh, g_wkh);
    cudaGetSymbolAddress((void**)&pwkl, g_wkl);
    cudaGetSymbolAddress((void**)&pw1h, g_w1h);
    cudaGetSymbolAddress((void**)&pw1l, g_w1l);
    cudaGetSymbolAddress((void**)&pw2h, g_w2h);
    cudaGetSymbolAddress((void**)&pw2l, g_w2l);

    cudaFuncSetAttribute(scores_softmax, cudaFuncAttributeMaxDynamicSharedMemorySize, FS_SMEM);

    const int n4 = Dd * Dd / 4;
    splitf<<<(n4 + 255) / 256, 256>>>((const float4*)Wq,   pwqh, pwql, n4);
    splitf<<<(n4 + 255) / 256, 256>>>((const float4*)Wk,   pwkh, pwkl, n4);
    splitf<<<(n4 + 255) / 256, 256>>>((const float4*)ff1w, pw1h, pw1l, n4);
    splitf<<<(n4 + 255) / 256, 256>>>((const float4*)ff2w, pw2h, pw2l, n4);

    ln_fused<<<NTOK, 256>>>(x, ln1s, ln1b, ln2s, ln2b);

    dim3 g0(Dd / 128, NTOK / 128);
    gemm3<3><<<g0, 256>>>(NTOK, Dd, Dd, phh, phl, pwqh, pwql,
                          nullptr, nullptr, nullptr, pqh, pql);
    gemm3<3><<<g0, 256>>>(NTOK, Dd, Dd, phh, phl, pwkh, pwkl,
                          nullptr, nullptr, nullptr, pkh, pkl);
    gemm3<1><<<g0, 256>>>(NTOK, Dd, Dd, ph2h, ph2l, pw1h, pw1l,
                          nullptr, ff1b, nullptr, pf1h, pf1l);
    gemm3<2><<<g0, 256>>>(NTOK, Dd, Dd, pf1h, pf1l, pw2h, pw2l,
                          out, ff2b, px2, nullptr, nullptr);

    dim3 gs(Sq / 16, NBH);
    scores_softmax<<<gs, 512, FS_SMEM>>>(pqh, pql, pkh, pkl, attn);
}

// round 6
// speedup vs baseline: 1.0822x; 1.0179x over previous
#include <cuda_runtime.h>
#include <cuda_fp16.h>
#include <cstdint>
#include <math.h>

#define Dd    2048
#define NTOK  4096
#define Sq    1024
#define HDh   64
#define NBH   128
#define EPSV  1e-5f
#define INV_SQRT_D 0.022097086912079608f

// ---------------- scratch ---------------------------------------------------
__device__ float g_x2[(size_t)NTOK * Dd];
__device__ __half g_hh [(size_t)NTOK * Dd], g_hl [(size_t)NTOK * Dd];
__device__ __half g_h2h[(size_t)NTOK * Dd], g_h2l[(size_t)NTOK * Dd];
__device__ __half g_f1h[(size_t)NTOK * Dd], g_f1l[(size_t)NTOK * Dd];
__device__ __half g_qh [(size_t)NTOK * Dd], g_ql [(size_t)NTOK * Dd];
__device__ __half g_kh [(size_t)NTOK * Dd], g_kl [(size_t)NTOK * Dd];
// single-plane fp16 weights ([K,N], n-major)
__device__ __half g_wq[(size_t)Dd * Dd], g_wk[(size_t)Dd * Dd];
__device__ __half g_w1[(size_t)Dd * Dd], g_w2[(size_t)Dd * Dd];

// ---------------- helpers ----------------------------------------------------
__device__ __forceinline__ uint32_t smem_u32(const void* p) {
    return (uint32_t)__cvta_generic_to_shared(p);
}
__device__ __forceinline__ void cp16(uint32_t dst, const void* src) {
    asm volatile("cp.async.cg.shared.global [%0], [%1], 16;" :: "r"(dst), "l"(src));
}
__device__ __forceinline__ void cp_commit() {
    asm volatile("cp.async.commit_group;");
}
template<int N> __device__ __forceinline__ void cp_wait() {
    asm volatile("cp.async.wait_group %0;" :: "n"(N));
}
__device__ __forceinline__ void ldmx4(uint32_t a, uint32_t& r0, uint32_t& r1,
                                      uint32_t& r2, uint32_t& r3) {
    asm volatile("ldmatrix.sync.aligned.m8n8.x4.shared.b16 {%0,%1,%2,%3},[%4];"
                 : "=r"(r0), "=r"(r1), "=r"(r2), "=r"(r3) : "r"(a));
}
__device__ __forceinline__ void ldmx4t(uint32_t a, uint32_t& r0, uint32_t& r1,
                                       uint32_t& r2, uint32_t& r3) {
    asm volatile("ldmatrix.sync.aligned.m8n8.x4.trans.shared.b16 {%0,%1,%2,%3},[%4];"
                 : "=r"(r0), "=r"(r1), "=r"(r2), "=r"(r3) : "r"(a));
}
// fp16 mma, fp32 accumulate
__device__ __forceinline__ void mma16816(float* c, const uint32_t* a, const uint32_t* b) {
    asm volatile(
        "mma.sync.aligned.m16n8k16.row.col.f32.f16.f16.f32 "
        "{%0,%1,%2,%3},{%4,%5,%6,%7},{%8,%9},{%0,%1,%2,%3};"
        : "+f"(c[0]), "+f"(c[1]), "+f"(c[2]), "+f"(c[3])
        : "r"(a[0]), "r"(a[1]), "r"(a[2]), "r"(a[3]), "r"(b[0]), "r"(b[1]));
}
__device__ __forceinline__ void split2h(float v0, float v1, __half2& hi, __half2& lo) {
    __half h0 = __float2half_rn(v0);
    __half h1 = __float2half_rn(v1);
    __half l0 = __float2half_rn(v0 - __half2float(h0));
    __half l1 = __float2half_rn(v1 - __half2float(h1));
    hi = __halves2half2(h0, h1);
    lo = __halves2half2(l0, l1);
}
__device__ __forceinline__ void split_store4h(__half* hi, __half* lo,
                                              size_t idx, float4 v) {
    __half2 h01, l01, h23, l23;
    split2h(v.x, v.y, h01, l01);
    split2h(v.z, v.w, h23, l23);
    *(__half2*)(hi + idx)     = h01;
    *(__half2*)(hi + idx + 2) = h23;
    *(__half2*)(lo + idx)     = l01;
    *(__half2*)(lo + idx + 2) = l23;
}

// ---------------- weight convert (fp32 -> fp16 single plane) -----------------
__global__ __launch_bounds__(256) void cvt_h(const float4* __restrict__ W,
                                             __half* __restrict__ o, int n4) {
    int i = blockIdx.x * 256 + threadIdx.x;
    if (i >= n4) return;
    float4 v = W[i];
    *(__half2*)(o + (size_t)i * 4)     = __floats2half2_rn(v.x, v.y);
    *(__half2*)(o + (size_t)i * 4 + 2) = __floats2half2_rn(v.z, v.w);
}

// ---------------- fused LN1 / residual / LN2 ---------------------------------
__global__ __launch_bounds__(256) void ln_fused(
    const float* __restrict__ x,
    const float* __restrict__ s1, const float* __restrict__ b1,
    const float* __restrict__ s2, const float* __restrict__ b2)
{
    __shared__ float rbuf[16];
    __shared__ float stats[2];
    const int tid = threadIdx.x;
    const size_t base = (size_t)blockIdx.x * Dd;
    const float4* xr = (const float4*)(x + base);
    float4 a0 = xr[tid];
    float4 a1 = xr[tid + 256];

    float s = a0.x + a0.y + a0.z + a0.w + a1.x + a1.y + a1.z + a1.w;
    float q = a0.x*a0.x + a0.y*a0.y + a0.z*a0.z + a0.w*a0.w
            + a1.x*a1.x + a1.y*a1.y + a1.z*a1.z + a1.w*a1.w;
    #pragma unroll
    for (int o = 16; o; o >>= 1) {
        s += __shfl_xor_sync(0xffffffffu, s, o);
        q += __shfl_xor_sync(0xffffffffu, q, o);
    }
    if ((tid & 31) == 0) { rbuf[tid >> 5] = s; rbuf[8 + (tid >> 5)] = q; }
    __syncthreads();
    if (tid == 0) {
        float ss = 0.f, qq = 0.f;
        #pragma unroll
        for (int i = 0; i < 8; i++) { ss += rbuf[i]; qq += rbuf[8 + i]; }
        float m = ss * (1.0f / Dd);
        stats[0] = m;
        stats[1] = rsqrtf(qq * (1.0f / Dd) - m * m + EPSV);
    }
    __syncthreads();
    float m = stats[0], r = stats[1];

    const float4* s1v = (const float4*)s1;
    const float4* b1v = (const float4*)b1;
    float4 sc0 = s1v[tid], sc1 = s1v[tid + 256];
    float4 bi0 = b1v[tid], bi1 = b1v[tid + 256];

    float4 h0, h1, x20, x21;
    h0.x = (a0.x - m) * r * sc0.x + bi0.x;  h0.y = (a0.y - m) * r * sc0.y + bi0.y;
    h0.z = (a0.z - m) * r * sc0.z + bi0.z;  h0.w = (a0.w - m) * r * sc0.w + bi0.w;
    h1.x = (a1.x - m) * r * sc1.x + bi1.x;  h1.y = (a1.y - m) * r * sc1.y + bi1.y;
    h1.z = (a1.z - m) * r * sc1.z + bi1.z;  h1.w = (a1.w - m) * r * sc1.w + bi1.w;
    x20.x = h0.x + a0.x; x20.y = h0.y + a0.y; x20.z = h0.z + a0.z; x20.w = h0.w + a0.w;
    x21.x = h1.x + a1.x; x21.y = h1.y + a1.y; x21.z = h1.z + a1.z; x21.w = h1.w + a1.w;

    split_store4h(g_hh, g_hl, base + (size_t)tid * 4, h0);
    split_store4h(g_hh, g_hl, base + (size_t)(tid + 256) * 4, h1);
    ((float4*)(g_x2 + base))[tid]       = x20;
    ((float4*)(g_x2 + base))[tid + 256] = x21;

    s = x20.x + x20.y + x20.z + x20.w + x21.x + x21.y + x21.z + x21.w;
    q = x20.x*x20.x + x20.y*x20.y + x20.z*x20.z + x20.w*x20.w
      + x21.x*x21.x + x21.y*x21.y + x21.z*x21.z + x21.w*x21.w;
    #pragma unroll
    for (int o = 16; o; o >>= 1) {
        s += __shfl_xor_sync(0xffffffffu, s, o);
        q += __shfl_xor_sync(0xffffffffu, q, o);
    }
    if ((tid & 31) == 0) { rbuf[tid >> 5] = s; rbuf[8 + (tid >> 5)] = q; }
    __syncthreads();
    if (tid == 0) {
        float ss = 0.f, qq = 0.f;
        #pragma unroll
        for (int i = 0; i < 8; i++) { ss += rbuf[i]; qq += rbuf[8 + i]; }
        float mm = ss * (1.0f / Dd);
        stats[0] = mm;
        stats[1] = rsqrtf(qq * (1.0f / Dd) - mm * mm + EPSV);
    }
    __syncthreads();
    m = stats[0]; r = stats[1];

    const float4* s2v = (const float4*)s2;
    const float4* b2v = (const float4*)b2;
    sc0 = s2v[tid]; sc1 = s2v[tid + 256];
    bi0 = b2v[tid]; bi1 = b2v[tid + 256];
    float4 o0, o1;
    o0.x = (x20.x - m) * r * sc0.x + bi0.x;  o0.y = (x20.y - m) * r * sc0.y + bi0.y;
    o0.z = (x20.z - m) * r * sc0.z + bi0.z;  o0.w = (x20.w - m) * r * sc0.w + bi0.w;
    o1.x = (x21.x - m) * r * sc1.x + bi1.x;  o1.y = (x21.y - m) * r * sc1.y + bi1.y;
    o1.z = (x21.z - m) * r * sc1.z + bi1.z;  o1.w = (x21.w - m) * r * sc1.w + bi1.w;
    split_store4h(g_h2h, g_h2l, base + (size_t)tid * 4, o0);
    split_store4h(g_h2h, g_h2l, base + (size_t)(tid + 256) * 4, o1);
}

// ---------------------------------------------------------------------------
// fp16 split-2 GEMM: C = (Ah+Al) * B,  A[M,K] k-major hi/lo, B[K,N] n-major.
// Block 128x128, BK=32, 256 threads = 8 warps (2Mx4N), warp tile 64x32.
// 2 mmas per fragment pair (ah*b + al*b).
// EPI: 1 = relu(acc+bias) -> split fp16 hi/lo
//      2 = acc + bias + addm -> fp32 C
//      3 = split fp16 hi/lo
// ---------------------------------------------------------------------------
template<int EPI>
__global__ __launch_bounds__(256) void gemm2(
    int M, int N, int K,
    const __half* __restrict__ Ah, const __half* __restrict__ Al,
    const __half* __restrict__ Bm,
    float* __restrict__ C,
    const float* __restrict__ bias, const float* __restrict__ addm,
    __half* __restrict__ Ohi, __half* __restrict__ Olo)
{
    __shared__ __half sAh[128 * 40], sAl[128 * 40];
    __shared__ __half sB[32 * 136];

    const int tid = threadIdx.x;
    const int m0 = blockIdx.y * 128, n0 = blockIdx.x * 128;
    const int s0 = tid, s1 = tid + 256;

    const __half* gAh0 = Ah + (size_t)(m0 + (s0 >> 2)) * K + (s0 & 3) * 8;
    const __half* gAh1 = Ah + (size_t)(m0 + (s1 >> 2)) * K + (s1 & 3) * 8;
    const __half* gAl0 = Al + (size_t)(m0 + (s0 >> 2)) * K + (s0 & 3) * 8;
    const __half* gAl1 = Al + (size_t)(m0 + (s1 >> 2)) * K + (s1 & 3) * 8;
    const __half* gB0  = Bm + (size_t)(s0 >> 4) * N + n0 + (s0 & 15) * 8;
    const __half* gB1  = Bm + (size_t)(s1 >> 4) * N + n0 + (s1 & 15) * 8;

    const int sa0 = (s0 >> 2) * 40 + (s0 & 3) * 8;
    const int sa1 = (s1 >> 2) * 40 + (s1 & 3) * 8;
    const int sb0 = (s0 >> 4) * 136 + (s0 & 15) * 8;
    const int sb1 = (s1 >> 4) * 136 + (s1 & 15) * 8;

    const int lane = tid & 31;
    const int wid = tid >> 5;
    const int wm = (wid & 1) * 64;
    const int wn = (wid >> 1) * 32;

    const uint32_t aBaseH = smem_u32(sAh) + (((wm + (lane & 15)) * 40 + ((lane >> 4) << 3)) << 1);
    const uint32_t aBaseL = smem_u32(sAl) + (((wm + (lane & 15)) * 40 + ((lane >> 4) << 3)) << 1);
    const uint32_t bBase  = smem_u32(sB)  + ((((lane & 15)) * 136 + wn + ((lane >> 4) << 3)) << 1);

    float acc[4][4][4];
    #pragma unroll
    for (int i = 0; i < 4; i++)
        #pragma unroll
        for (int j = 0; j < 4; j++)
            #pragma unroll
            for (int t = 0; t < 4; t++) acc[i][j][t] = 0.f;

    uint4 vah0, vah1, val0, val1, vb0, vb1;

    auto LDG = [&](int k0) {
        vah0 = *(const uint4*)(gAh0 + k0);
        vah1 = *(const uint4*)(gAh1 + k0);
        val0 = *(const uint4*)(gAl0 + k0);
        val1 = *(const uint4*)(gAl1 + k0);
        vb0  = *(const uint4*)(gB0 + (size_t)k0 * N);
        vb1  = *(const uint4*)(gB1 + (size_t)k0 * N);
    };
    auto STS = [&]() {
        *(uint4*)(sAh + sa0) = vah0;  *(uint4*)(sAh + sa1) = vah1;
        *(uint4*)(sAl + sa0) = val0;  *(uint4*)(sAl + sa1) = val1;
        *(uint4*)(sB + sb0) = vb0;    *(uint4*)(sB + sb1) = vb1;
    };
    auto COMP = [&](int kb) {
        uint32_t afh[4][4], afl[4][4], bf[4][2];
        #pragma unroll
        for (int mt = 0; mt < 4; mt++) {
            ldmx4(aBaseH + ((mt * 16 * 40 + kb) << 1),
                  afh[mt][0], afh[mt][1], afh[mt][2], afh[mt][3]);
            ldmx4(aBaseL + ((mt * 16 * 40 + kb) << 1),
                  afl[mt][0], afl[mt][1], afl[mt][2], afl[mt][3]);
        }
        #pragma unroll
        for (int np = 0; np < 2; np++) {
            ldmx4t(bBase + ((kb * 136 + np * 16) << 1),
                   bf[2*np][0], bf[2*np][1], bf[2*np+1][0], bf[2*np+1][1]);
        }
        #pragma unroll
        for (int mt = 0; mt < 4; mt++)
            #pragma unroll
            for (int nt = 0; nt < 4; nt++) {
                mma16816(acc[mt][nt], afh[mt], bf[nt]);
                mma16816(acc[mt][nt], afl[mt], bf[nt]);
            }
    };

    LDG(0);
    STS();
    __syncthreads();
    for (int k0 = 32; k0 < K; k0 += 32) {
        LDG(k0);
        COMP(0);
        COMP(16);
        __syncthreads();
        STS();
        __syncthreads();
    }
    COMP(0);
    COMP(16);

    const int g = lane >> 2, tig = lane & 3;
    #pragma unroll
    for (int mt = 0; mt < 4; mt++) {
        #pragma unroll
        for (int nt = 0; nt < 4; nt++) {
            const int row = m0 + wm + mt * 16 + g;
            const int col = n0 + wn + nt * 8 + tig * 2;
            const float* a4 = acc[mt][nt];
            if (EPI == 3) {
                __half2 h01, l01, h23, l23;
                split2h(a4[0], a4[1], h01, l01);
                split2h(a4[2], a4[3], h23, l23);
                *(__half2*)(Ohi + (size_t)row * N + col)       = h01;
                *(__half2*)(Olo + (size_t)row * N + col)       = l01;
                *(__half2*)(Ohi + (size_t)(row + 8) * N + col) = h23;
                *(__half2*)(Olo + (size_t)(row + 8) * N + col) = l23;
            } else if (EPI == 1) {
                float b0 = bias[col], b1 = bias[col + 1];
                float v0 = fmaxf(a4[0] + b0, 0.f), v1 = fmaxf(a4[1] + b1, 0.f);
                float v2 = fmaxf(a4[2] + b0, 0.f), v3 = fmaxf(a4[3] + b1, 0.f);
                __half2 h01, l01, h23, l23;
                split2h(v0, v1, h01, l01);
                split2h(v2, v3, h23, l23);
                *(__half2*)(Ohi + (size_t)row * N + col)       = h01;
                *(__half2*)(Olo + (size_t)row * N + col)       = l01;
                *(__half2*)(Ohi + (size_t)(row + 8) * N + col) = h23;
                *(__half2*)(Olo + (size_t)(row + 8) * N + col) = l23;
            } else { // EPI == 2
                float b0 = bias[col], b1 = bias[col + 1];
                float2 ad0 = *(const float2*)(addm + (size_t)row * N + col);
                float2 ad1 = *(const float2*)(addm + (size_t)(row + 8) * N + col);
                *(float2*)(C + (size_t)row * N + col) =
                    make_float2(a4[0] + b0 + ad0.x, a4[1] + b1 + ad0.y);
                *(float2*)(C + (size_t)(row + 8) * N + col) =
                    make_float2(a4[2] + b0 + ad1.x, a4[3] + b1 + ad1.y);
            }
        }
    }
}

// -----------------------------------------------------------------------------
// Fused scores + softmax, register-resident scores (R4 structure, fp16 3-term:
// qh*kh + qh*kl + ql*kh — exact to 2^-24, keeps attn_probs at ~1e-6 accuracy).
// grid = (Sq/16, NBH), 512 threads.
// -----------------------------------------------------------------------------
#define FS_QH   0u
#define FS_QL   2304u
#define FS_KH0  4608u
#define FS_KL0  41472u
#define FS_KSTR 73728u
#define FS_RED  152064u
#define FS_SMEM 153088u

__global__ __launch_bounds__(512) void scores_softmax(
    const __half* __restrict__ Qh, const __half* __restrict__ Ql,
    const __half* __restrict__ Kh, const __half* __restrict__ Kl,
    float* __restrict__ attn)
{
    extern __shared__ __align__(16) char dsm[];
    const uint32_t sbase = smem_u32(dsm);
    float* red = (float*)(dsm + FS_RED);

    const int tid = threadIdx.x;
    const int lane = tid & 31;
    const int wid = tid >> 5;
    const int bh = blockIdx.y;
    const int m0 = blockIdx.x * 16;
    const size_t off = (size_t)(bh >> 5) * ((size_t)Sq * Dd) + (size_t)(bh & 31) * HDh;

    if (tid < 256) {
        int plane = tid >> 7, i2 = tid & 127;
        int row = i2 >> 3, col = (i2 & 7) * 8;
        const __half* src = (plane ? Ql : Qh) + off + (size_t)(m0 + row) * Dd + col;
        cp16(sbase + (plane ? FS_QL : FS_QH) + (row * 72 + col) * 2, src);
    }
    auto ISSUEK = [&](int chunk, int buf) {
        #pragma unroll
        for (int p = 0; p < 8; p++) {
            int idx = tid + p * 512;
            int plane = idx >> 11;
            int i2 = idx & 2047;
            int row = i2 >> 3, col = (i2 & 7) * 8;
            const __half* src = (plane ? Kl : Kh) + off
                              + (size_t)(chunk * 256 + row) * Dd + col;
            cp16(sbase + (plane ? FS_KL0 : FS_KH0) + (uint32_t)buf * FS_KSTR
                 + (row * 72 + col) * 2, src);
        }
        cp_commit();
    };
    ISSUEK(0, 0);
    ISSUEK(1, 1);
    cp_wait<1>();
    __syncthreads();

    const uint32_t aOff = (((lane & 15)) * 72 + ((lane >> 4) << 3)) * 2;
    uint32_t afh[4][4], afl[4][4];
    #pragma unroll
    for (int kb4 = 0; kb4 < 4; kb4++) {
        ldmx4(sbase + FS_QH + aOff + ((kb4 * 16) << 1),
              afh[kb4][0], afh[kb4][1], afh[kb4][2], afh[kb4][3]);
        ldmx4(sbase + FS_QL + aOff + ((kb4 * 16) << 1),
              afl[kb4][0], afl[kb4][1], afl[kb4][2], afl[kb4][3]);
    }

    const int bRow = ((lane >> 4) << 3) + (lane & 7);
    const int bKof = ((lane >> 3) & 1) << 3;
    const uint32_t bOff = ((wid * 16 + bRow) * 72 + bKof) * 2;

    float acc[4][2][4];
    #pragma unroll
    for (int it = 0; it < 4; it++)
        #pragma unroll
        for (int nt = 0; nt < 2; nt++)
            #pragma unroll
            for (int t = 0; t < 4; t++) acc[it][nt][t] = 0.f;

    #pragma unroll
    for (int it = 0; it < 4; it++) {
        const int buf = it & 1;
        const uint32_t kh = sbase + FS_KH0 + (uint32_t)buf * FS_KSTR + bOff;
        const uint32_t kl = sbase + FS_KL0 + (uint32_t)buf * FS_KSTR + bOff;
        #pragma unroll
        for (int kb4 = 0; kb4 < 4; kb4++) {
            uint32_t bh4[4], bl4[4];
            ldmx4(kh + ((kb4 * 16) << 1), bh4[0], bh4[1], bh4[2], bh4[3]);
            ldmx4(kl + ((kb4 * 16) << 1), bl4[0], bl4[1], bl4[2], bl4[3]);
            #pragma unroll
            for (int nt = 0; nt < 2; nt++) {
                mma16816(acc[it][nt], afh[kb4], &bh4[nt * 2]);
                mma16816(acc[it][nt], afh[kb4], &bl4[nt * 2]);
                mma16816(acc[it][nt], afl[kb4], &bh4[nt * 2]);
            }
        }
        if (it < 2) {
            __syncthreads();
            ISSUEK(it + 2, buf);
            cp_wait<1>();
            __syncthreads();
        } else if (it == 2) {
            cp_wait<0>();
            __syncthreads();
        }
    }

    const int g = lane >> 2, tig = lane & 3;
    const float c = INV_SQRT_D;
    float mx0 = -1e30f, mx1 = -1e30f;
    #pragma unroll
    for (int it = 0; it < 4; it++)
        #pragma unroll
        for (int nt = 0; nt < 2; nt++) {
            float* a4 = acc[it][nt];
            a4[0] *= c; a4[1] *= c; a4[2] *= c; a4[3] *= c;
            mx0 = fmaxf(mx0, fmaxf(a4[0], a4[1]));
            mx1 = fmaxf(mx1, fmaxf(a4[2], a4[3]));
        }
    mx0 = fmaxf(mx0, __shfl_xor_sync(0xffffffffu, mx0, 1));
    mx0 = fmaxf(mx0, __shfl_xor_sync(0xffffffffu, mx0, 2));
    mx1 = fmaxf(mx1, __shfl_xor_sync(0xffffffffu, mx1, 1));
    mx1 = fmaxf(mx1, __shfl_xor_sync(0xffffffffu, mx1, 2));
    if (tig == 0) { red[g * 16 + wid] = mx0; red[(g + 8) * 16 + wid] = mx1; }
    __syncthreads();
    float m0f = -1e30f, m1f = -1e30f;
    #pragma unroll
    for (int w = 0; w < 16; w++) {
        m0f = fmaxf(m0f, red[g * 16 + w]);
        m1f = fmaxf(m1f, red[(g + 8) * 16 + w]);
    }
    __syncthreads();

    float s0 = 0.f, s1 = 0.f;
    #pragma unroll
    for (int it = 0; it < 4; it++)
        #pragma unroll
        for (int nt = 0; nt < 2; nt++) {
            float* a4 = acc[it][nt];
            a4[0] = __expf(a4[0] - m0f); a4[1] = __expf(a4[1] - m0f);
            a4[2] = __expf(a4[2] - m1f); a4[3] = __expf(a4[3] - m1f);
            s0 += a4[0] + a4[1];
            s1 += a4[2] + a4[3];
        }
    s0 += __shfl_xor_sync(0xffffffffu, s0, 1);
    s0 += __shfl_xor_sync(0xffffffffu, s0, 2);
    s1 += __shfl_xor_sync(0xffffffffu, s1, 1);
    s1 += __shfl_xor_sync(0xffffffffu, s1, 2);
    if (tig == 0) { red[g * 16 + wid] = s0; red[(g + 8) * 16 + wid] = s1; }
    __syncthreads();
    float t0 = 0.f, t1 = 0.f;
    #pragma unroll
    for (int w = 0; w < 16; w++) {
        t0 += red[g * 16 + w];
        t1 += red[(g + 8) * 16 + w];
    }
    const float inv0 = __fdividef(1.0f, t0);
    const float inv1 = __fdividef(1.0f, t1);

    float* base0 = attn + (size_t)bh * Sq * Sq + (size_t)(m0 + g) * Sq;
    float* base1 = base0 + (size_t)8 * Sq;
    #pragma unroll
    for (int it = 0; it < 4; it++)
        #pragma unroll
        for (int nt = 0; nt < 2; nt++) {
            const int col = it * 256 + wid * 16 + nt * 8 + tig * 2;
            const float* a4 = acc[it][nt];
            *(float2*)(base0 + col) = make_float2(a4[0] * inv0, a4[1] * inv0);
            *(float2*)(base1 + col) = make_float2(a4[2] * inv1, a4[3] * inv1);
        }
}

// -----------------------------------------------------------------------------
extern "C" void kernel_launch(void* const* d_in, const int* in_sizes, int n_in,
                              void* d_out, int out_size)
{
    (void)in_sizes; (void)n_in; (void)out_size;
    const float* x    = (const float*)d_in[0];
    const float* Wq   = (const float*)d_in[1];
    const float* Wk   = (const float*)d_in[2];
    /* d_in[3] = Wv : dead in the reference */
    const float* ln1s = (const float*)d_in[4];
    const float* ln1b = (const float*)d_in[5];
    const float* ln2s = (const float*)d_in[6];
    const float* ln2b = (const float*)d_in[7];
    const float* ff1w = (const float*)d_in[8];
    const float* ff1b = (const float*)d_in[9];
    const float* ff2w = (const float*)d_in[10];
    const float* ff2b = (const float*)d_in[11];

    float* out  = (float*)d_out;
    float* attn = out + (size_t)NTOK * Dd;

    float* px2;
    __half *phh, *phl, *ph2h, *ph2l, *pf1h, *pf1l, *pqh, *pql, *pkh, *pkl;
    __half *pwq, *pwk, *pw1, *pw2;
    cudaGetSymbolAddress((void**)&px2,  g_x2);
    cudaGetSymbolAddress((void**)&phh,  g_hh);
    cudaGetSymbolAddress((void**)&phl,  g_hl);
    cudaGetSymbolAddress((void**)&ph2h, g_h2h);
    cudaGetSymbolAddress((void**)&ph2l, g_h2l);
    cudaGetSymbolAddress((void**)&pf1h, g_f1h);
    cudaGetSymbolAddress((void**)&pf1l, g_f1l);
    cudaGetSymbolAddress((void**)&pqh,  g_qh);
    cudaGetSymbolAddress((void**)&pql,  g_ql);
    cudaGetSymbolAddress((void**)&pkh,  g_kh);
    cudaGetSymbolAddress((void**)&pkl,  g_kl);
    cudaGetSymbolAddress((void**)&pwq,  g_wq);
    cudaGetSymbolAddress((void**)&pwk,  g_wk);
    cudaGetSymbolAddress((void**)&pw1,  g_w1);
    cudaGetSymbolAddress((void**)&pw2,  g_w2);

    cudaFuncSetAttribute(scores_softmax, cudaFuncAttributeMaxDynamicSharedMemorySize, FS_SMEM);

    const int n4 = Dd * Dd / 4;
    cvt_h<<<(n4 + 255) / 256, 256>>>((const float4*)Wq,   pwq, n4);
    cvt_h<<<(n4 + 255) / 256, 256>>>((const float4*)Wk,   pwk, n4);
    cvt_h<<<(n4 + 255) / 256, 256>>>((const float4*)ff1w, pw1, n4);
    cvt_h<<<(n4 + 255) / 256, 256>>>((const float4*)ff2w, pw2, n4);

    ln_fused<<<NTOK, 256>>>(x, ln1s, ln1b, ln2s, ln2b);

    dim3 g0(Dd / 128, NTOK / 128);
    gemm2<3><<<g0, 256>>>(NTOK, Dd, Dd, phh, phl, pwq,
                          nullptr, nullptr, nullptr, pqh, pql);
    gemm2<3><<<g0, 256>>>(NTOK, Dd, Dd, phh, phl, pwk,
                          nullptr, nullptr, nullptr, pkh, pkl);
    gemm2<1><<<g0, 256>>>(NTOK, Dd, Dd, ph2h, ph2l, pw1,
                          nullptr, ff1b, nullptr, pf1h, pf1l);
    gemm2<2><<<g0, 256>>>(NTOK, Dd, Dd, pf1h, pf1l, pw2,
                          out, ff2b, px2, nullptr, nullptr);

    dim3 gs(Sq / 16, NBH);
    scores_softmax<<<gs, 512, FS_SMEM>>>(pqh, pql, pkh, pkl, attn);
}